// round 9
// baseline (speedup 1.0000x reference)
#include <cuda_runtime.h>
#include <cuda_bf16.h>
#include <math.h>
#include <cstdint>

#define BB   2
#define SEQ  2048
#define HIDN 2048
#define NH   16
#define NKV  4
#define HD   128

// ============================================================
// helpers
// ============================================================
__device__ __forceinline__ uint32_t smem_u32(const void* p) {
    uint32_t a;
    asm("{ .reg .u64 t; cvta.to.shared.u64 t, %1; cvt.u32.u64 %0, t; }" : "=r"(a) : "l"(p));
    return a;
}
__device__ __forceinline__ void ldsm_x4(uint32_t& r0, uint32_t& r1, uint32_t& r2, uint32_t& r3,
                                        uint32_t addr) {
    asm volatile("ldmatrix.sync.aligned.m8n8.x4.shared.b16 {%0,%1,%2,%3}, [%4];"
                 : "=r"(r0), "=r"(r1), "=r"(r2), "=r"(r3) : "r"(addr));
}
__device__ __forceinline__ void ldsm_x4_t(uint32_t& r0, uint32_t& r1, uint32_t& r2, uint32_t& r3,
                                          uint32_t addr) {
    asm volatile("ldmatrix.sync.aligned.m8n8.x4.trans.shared.b16 {%0,%1,%2,%3}, [%4];"
                 : "=r"(r0), "=r"(r1), "=r"(r2), "=r"(r3) : "r"(addr));
}
__device__ __forceinline__ void mma_bf16(float* c, const uint32_t* a, const uint32_t* b) {
    asm volatile("mma.sync.aligned.m16n8k16.row.col.f32.bf16.bf16.f32 "
                 "{%0,%1,%2,%3}, {%4,%5,%6,%7}, {%8,%9}, {%0,%1,%2,%3};"
                 : "+f"(c[0]), "+f"(c[1]), "+f"(c[2]), "+f"(c[3])
                 : "r"(a[0]), "r"(a[1]), "r"(a[2]), "r"(a[3]), "r"(b[0]), "r"(b[1]));
}
__device__ __forceinline__ void cp_async16(uint32_t saddr, const void* gptr) {
    asm volatile("cp.async.cg.shared.global [%0], [%1], 16;"
                 :: "r"(saddr), "l"(__cvta_generic_to_global(gptr)));
}
// fast 2^t on the FMA pipe, t <= 0
__device__ __forceinline__ float fexp2(float t) {
    t = fmaxf(t, -126.0f);
    float fi = floorf(t);
    float f = t - fi;
    float p =             1.5403530e-4f;
    p = fmaf(p, f, 1.3333558e-3f);
    p = fmaf(p, f, 9.6181291e-3f);
    p = fmaf(p, f, 5.5504109e-2f);
    p = fmaf(p, f, 2.4022651e-1f);
    p = fmaf(p, f, 6.9314718e-1f);
    p = fmaf(p, f, 1.0f);
    return p * __int_as_float(((int)fi + 127) << 23);
}

// -------- scratch (device globals) --------
__device__ __nv_bfloat16 g_xh[(size_t)BB * SEQ * HIDN], g_xl[(size_t)BB * SEQ * HIDN];
__device__ __nv_bfloat16 g_wqh[(size_t)HIDN * NH * HD], g_wql[(size_t)HIDN * NH * HD];
__device__ __nv_bfloat16 g_wkh[(size_t)HIDN * NKV * HD], g_wkl[(size_t)HIDN * NKV * HD];
__device__ __nv_bfloat16 g_wvh[(size_t)HIDN * NKV * HD], g_wvl[(size_t)HIDN * NKV * HD];
__device__ __nv_bfloat16 g_woh[(size_t)NH * HD * HIDN], g_wol[(size_t)NH * HD * HIDN];

// head-major split operands for attention: [b, head, s, d]
__device__ __nv_bfloat16 g_qsh[(size_t)BB * NH * SEQ * HD],  g_qsl[(size_t)BB * NH * SEQ * HD];
__device__ __nv_bfloat16 g_ksh[(size_t)BB * NKV * SEQ * HD], g_ksl[(size_t)BB * NKV * SEQ * HD];
__device__ __nv_bfloat16 g_vsh[(size_t)BB * NKV * SEQ * HD], g_vsl[(size_t)BB * NKV * SEQ * HD];
// attention output, split, [B*S, H*D]
__device__ __nv_bfloat16 g_oh[(size_t)BB * SEQ * NH * HD],  g_ol[(size_t)BB * SEQ * NH * HD];

// ============================================================
// fp32 -> (hi, lo) bf16 split
// ============================================================
__global__ void split_fp32(const float* __restrict__ x,
                           __nv_bfloat16* __restrict__ h, __nv_bfloat16* __restrict__ l, int n)
{
    int i = blockIdx.x * blockDim.x + threadIdx.x;
    if (i < n) {
        float v = x[i];
        __nv_bfloat16 hi = __float2bfloat16(v);
        h[i] = hi;
        l[i] = __float2bfloat16(v - __bfloat162float(hi));
    }
}

// ============================================================
// W[K,N] fp32 -> Wt_hi/Wt_lo [N,K] bf16 (transpose + split)
// ============================================================
__global__ void transpose_split(const float* __restrict__ W,
                                __nv_bfloat16* __restrict__ Th, __nv_bfloat16* __restrict__ Tl,
                                int K, int N)
{
    __shared__ float t[32][33];
    const int n0 = blockIdx.x * 32, k0 = blockIdx.y * 32;
    const int tx = threadIdx.x, ty = threadIdx.y;
    for (int i = ty; i < 32; i += 8)
        t[i][tx] = W[(size_t)(k0 + i) * N + n0 + tx];
    __syncthreads();
    for (int i = ty; i < 32; i += 8) {
        float v = t[tx][i];
        __nv_bfloat16 hi = __float2bfloat16(v);
        float r = v - __bfloat162float(hi);
        Th[(size_t)(n0 + i) * K + k0 + tx] = hi;
        Tl[(size_t)(n0 + i) * K + k0 + tx] = __float2bfloat16(r);
    }
}

#define LDA 40

// ============================================================
// gemm3: 128x128 CTA tile, 512 threads / 16 warps (4x4),
// 32x32 warp tile, BK=32, 3-stage cp.async, ONE barrier/chunk.
// C = (Ah+Al) @ (Bh+Bl)^T via 3-term split, fp32 accum.
// Epilogue: epi==0 -> fp32 row-major C.
//           epi==1 -> split bf16 head-major [b, n>>7, s, n&127].
// ============================================================
#define G3_TILE (128 * LDA * 2)       // 10240 B
#define G3_STAGE (4 * G3_TILE)        // 40960 B
#define G3_SMEM (3 * G3_STAGE)        // 122880 B

__global__ void __launch_bounds__(512, 1) gemm3(
    const __nv_bfloat16* __restrict__ Ah_, const __nv_bfloat16* __restrict__ Al_,
    const __nv_bfloat16* __restrict__ Bh_, const __nv_bfloat16* __restrict__ Bl_,
    float* __restrict__ Cf, __nv_bfloat16* __restrict__ Ch, __nv_bfloat16* __restrict__ Cl,
    int Nd, int Kd, int heads, int epi)
{
    extern __shared__ char sm[];
    const uint32_t sb = smem_u32(sm);
    const int tid = threadIdx.x, lane = tid & 31, wid = tid >> 5;
    const int m0 = blockIdx.y * 128, n0 = blockIdx.x * 128;
    const int m_off = (wid >> 2) * 32;   // 0,32,64,96
    const int n_off = (wid & 3) * 32;    // 0,32,64,96

    const int r0 = tid >> 2;             // 0..127
    const int c8 = (tid & 3) * 8;        // 0,8,16,24

    const __nv_bfloat16* gp[4] = {
        Ah_ + (size_t)m0 * Kd, Al_ + (size_t)m0 * Kd,
        Bh_ + (size_t)n0 * Kd, Bl_ + (size_t)n0 * Kd };

    const int nchunk = Kd >> 5;

    auto load_chunk = [&](int c) {
        const int k0 = c << 5;
        const uint32_t stg = sb + (uint32_t)(c % 3) * G3_STAGE;
        const uint32_t so = (uint32_t)(r0 * LDA + c8) * 2;
        const size_t go = (size_t)r0 * Kd + k0 + c8;
#pragma unroll
        for (int t = 0; t < 4; t++)
            cp_async16(stg + (uint32_t)t * G3_TILE + so, gp[t] + go);
        asm volatile("cp.async.commit_group;" ::: "memory");
    };

    const int a_row = ((lane >> 3) & 1) * 8 + (lane & 7);
    const int a_kh  = (lane >> 4) * 8;
    const int b_row = ((lane >> 4) & 1) * 8 + (lane & 7);
    const int b_kh  = ((lane >> 3) & 1) * 8;

    float acc[2][4][4];
#pragma unroll
    for (int i = 0; i < 2; i++)
#pragma unroll
        for (int j = 0; j < 4; j++)
#pragma unroll
            for (int q = 0; q < 4; q++) acc[i][j][q] = 0.f;

    load_chunk(0);
    load_chunk(1);

    for (int c = 0; c < nchunk; c++) {
        if (c < nchunk - 1) {
            asm volatile("cp.async.wait_group 1;" ::: "memory");
        } else {
            asm volatile("cp.async.wait_group 0;" ::: "memory");
        }
        __syncthreads();
        if (c + 2 < nchunk) load_chunk(c + 2);   // stage freed by the barrier

        const uint32_t stg = sb + (uint32_t)(c % 3) * G3_STAGE;
        const uint32_t sAh = stg;
        const uint32_t sAl = stg + G3_TILE;
        const uint32_t sBh = stg + 2 * G3_TILE;
        const uint32_t sBl = stg + 3 * G3_TILE;

#pragma unroll
        for (int ks = 0; ks < 2; ks++) {
            uint32_t ah[2][4], al[2][4], bh[4][2], bl[4][2];
#pragma unroll
            for (int mi = 0; mi < 2; mi++) {
                const uint32_t off =
                    (uint32_t)((m_off + mi * 16 + a_row) * LDA + ks * 16 + a_kh) * 2;
                ldsm_x4(ah[mi][0], ah[mi][1], ah[mi][2], ah[mi][3], sAh + off);
                ldsm_x4(al[mi][0], al[mi][1], al[mi][2], al[mi][3], sAl + off);
            }
#pragma unroll
            for (int nb = 0; nb < 2; nb++) {
                const uint32_t off =
                    (uint32_t)((n_off + nb * 16 + b_row) * LDA + ks * 16 + b_kh) * 2;
                ldsm_x4(bh[2 * nb][0], bh[2 * nb][1], bh[2 * nb + 1][0], bh[2 * nb + 1][1],
                        sBh + off);
                ldsm_x4(bl[2 * nb][0], bl[2 * nb][1], bl[2 * nb + 1][0], bl[2 * nb + 1][1],
                        sBl + off);
            }
#pragma unroll
            for (int mi = 0; mi < 2; mi++)
#pragma unroll
                for (int ni = 0; ni < 4; ni++) {
                    mma_bf16(acc[mi][ni], ah[mi], bh[ni]);
                    mma_bf16(acc[mi][ni], ah[mi], bl[ni]);
                    mma_bf16(acc[mi][ni], al[mi], bh[ni]);
                }
        }
    }

    const int erow = lane >> 2, ecol = (lane & 3) * 2;
    if (epi == 0) {
#pragma unroll
        for (int mi = 0; mi < 2; mi++)
#pragma unroll
            for (int ni = 0; ni < 4; ni++) {
                const int row = m0 + m_off + mi * 16 + erow;
                const int col = n0 + n_off + ni * 8 + ecol;
                float2 v0 = make_float2(acc[mi][ni][0], acc[mi][ni][1]);
                float2 v1 = make_float2(acc[mi][ni][2], acc[mi][ni][3]);
                *(float2*)(Cf + (size_t)row * Nd + col)       = v0;
                *(float2*)(Cf + (size_t)(row + 8) * Nd + col) = v1;
            }
    } else {
        // split bf16, head-major [b, h, s, d]; row = b*SEQ + s, col = h*HD + d
#pragma unroll
        for (int mi = 0; mi < 2; mi++)
#pragma unroll
            for (int ni = 0; ni < 4; ni++) {
                const int col = n0 + n_off + ni * 8 + ecol;
                const int hh = col >> 7, d = col & 127;
#pragma unroll
                for (int rr = 0; rr < 2; rr++) {
                    const int row = m0 + m_off + mi * 16 + erow + rr * 8;
                    const int bb = row >> 11, s = row & (SEQ - 1);
                    const size_t g = ((size_t)(bb * heads + hh) * SEQ + s) * HD + d;
                    float v0 = acc[mi][ni][rr * 2 + 0];
                    float v1 = acc[mi][ni][rr * 2 + 1];
                    __nv_bfloat16 h0 = __float2bfloat16(v0);
                    __nv_bfloat16 h1 = __float2bfloat16(v1);
                    __nv_bfloat162 hp; hp.x = h0; hp.y = h1;
                    *(__nv_bfloat162*)(Ch + g) = hp;
                    __nv_bfloat162 lp;
                    lp.x = __float2bfloat16(v0 - __bfloat162float(h0));
                    lp.y = __float2bfloat16(v1 - __bfloat162float(h1));
                    *(__nv_bfloat162*)(Cl + g) = lp;
                }
            }
    }
}

// ============================================================
// RoPE in-place on split bf16 head-major rows [*, 128]
// ============================================================
__global__ void rope_inplace(__nv_bfloat16* __restrict__ h, __nv_bfloat16* __restrict__ l)
{
    const int idx = blockIdx.x;            // (b*heads + hh)*SEQ + s
    const int s = idx & (SEQ - 1);
    const size_t base = (size_t)idx * HD;
    const int i = threadIdx.x;             // 0..63

    float x0 = __bfloat162float(h[base + 2 * i])     + __bfloat162float(l[base + 2 * i]);
    float x1 = __bfloat162float(h[base + 2 * i + 1]) + __bfloat162float(l[base + 2 * i + 1]);
    float inv = exp2f(-(float)i * (13.287712379549449f / 64.f));
    float ang = (float)s * inv;
    float sn, cs;
    sincosf(ang, &sn, &cs);
    float o0 = x0 * cs - x1 * sn;
    float o1 = x0 * sn + x1 * cs;
    __syncthreads();   // all reads before any writes
    __nv_bfloat16 h0 = __float2bfloat16(o0);
    __nv_bfloat16 h1 = __float2bfloat16(o1);
    h[base + i]      = h0;
    h[base + i + 64] = h1;
    l[base + i]      = __float2bfloat16(o0 - __bfloat162float(h0));
    l[base + i + 64] = __float2bfloat16(o1 - __bfloat162float(h1));
}

// ============================================================
// HMMA flash attention (unchanged from R6)
// ============================================================
#define ALDQ 136
#define ALDS 73
#define ALDP 72
#define A_QH 0
#define A_QL (A_QH + 128 * ALDQ * 2)
#define A_KH (A_QL + 128 * ALDQ * 2)
#define A_KL (A_KH + 64 * ALDQ * 2)
#define A_VH (A_KL + 64 * ALDQ * 2)
#define A_VL (A_VH + 64 * ALDQ * 2)
#define A_SP (A_VL + 64 * ALDQ * 2)
#define A_PH (A_SP + 128 * ALDS * 4)
#define A_PL (A_PH + 128 * ALDP * 2)
#define A_MS (A_PL + 128 * ALDP * 2)
#define A_LS (A_MS + 512)
#define A_FS (A_LS + 512)
#define A_RED (A_FS + 512)
#define ATTN_SMEM_B (A_RED + 1024)

#define SCL2E 0.12751744f

__global__ void __launch_bounds__(256, 1) attn_hmma(
    const __nv_bfloat16* __restrict__ Qh_, const __nv_bfloat16* __restrict__ Ql_,
    const __nv_bfloat16* __restrict__ Kh_, const __nv_bfloat16* __restrict__ Kl_,
    const __nv_bfloat16* __restrict__ Vh_, const __nv_bfloat16* __restrict__ Vl_,
    __nv_bfloat16* __restrict__ Oh_, __nv_bfloat16* __restrict__ Ol_)
{
    extern __shared__ char sm[];
    const uint32_t sb = smem_u32(sm);
    float* Sp  = (float*)(sm + A_SP);
    float* m_s = (float*)(sm + A_MS);
    float* l_s = (float*)(sm + A_LS);
    float* f_s = (float*)(sm + A_FS);
    float* red = (float*)(sm + A_RED);
    __nv_bfloat16* PhP = (__nv_bfloat16*)(sm + A_PH);
    __nv_bfloat16* PlP = (__nv_bfloat16*)(sm + A_PL);

    const int qb = blockIdx.x, h = blockIdx.y, b = blockIdx.z;
    const int kvh = h >> 2;
    const int tid = threadIdx.x, lane = tid & 31, wid = tid >> 5;
    const int q0 = qb * 128;

    const size_t qg = ((size_t)(b * NH + h) * SEQ + q0) * HD;
    const size_t kg = (size_t)(b * NKV + kvh) * SEQ * HD;

    for (int i = tid; i < 128 * 16; i += 256) {
        int r = i >> 4, c = (i & 15) * 8;
        uint32_t so = (uint32_t)(r * ALDQ + c) * 2;
        cp_async16(sb + A_QH + so, Qh_ + qg + (size_t)r * HD + c);
        cp_async16(sb + A_QL + so, Ql_ + qg + (size_t)r * HD + c);
    }
    asm volatile("cp.async.commit_group;" ::: "memory");
    if (tid < 128) { m_s[tid] = -1e30f; l_s[tid] = 0.f; }

    float accO[2][8][4];
#pragma unroll
    for (int i = 0; i < 2; i++)
#pragma unroll
        for (int j = 0; j < 8; j++)
#pragma unroll
            for (int q = 0; q < 4; q++) accO[i][j][q] = 0.f;

    const int m_off = (wid >> 1) * 32;
    const int nS = (wid & 1) * 32;
    const int nO = (wid & 1) * 64;
    const int a_row = ((lane >> 3) & 1) * 8 + (lane & 7);
    const int a_kh  = (lane >> 4) * 8;
    const int b_row = ((lane >> 4) & 1) * 8 + (lane & 7);
    const int b_kh  = ((lane >> 3) & 1) * 8;
    const int erow = lane >> 2, ecol = (lane & 3) * 2;

    asm volatile("cp.async.wait_group 0;" ::: "memory");
    __syncthreads();

    const int ntiles = 2 * qb + 2;
    for (int jb = 0; jb < ntiles; jb++) {
        const int k0 = jb * 64;
        for (int i = tid; i < 64 * 16; i += 256) {
            int r = i >> 4, c = (i & 15) * 8;
            uint32_t so = (uint32_t)(r * ALDQ + c) * 2;
            const size_t g = kg + (size_t)(k0 + r) * HD + c;
            cp_async16(sb + A_KH + so, Kh_ + g);
            cp_async16(sb + A_KL + so, Kl_ + g);
            cp_async16(sb + A_VH + so, Vh_ + g);
            cp_async16(sb + A_VL + so, Vl_ + g);
        }
        asm volatile("cp.async.commit_group;" ::: "memory");
        asm volatile("cp.async.wait_group 0;" ::: "memory");
        __syncthreads();

        float accS[2][4][4];
#pragma unroll
        for (int i = 0; i < 2; i++)
#pragma unroll
            for (int j = 0; j < 4; j++)
#pragma unroll
                for (int q = 0; q < 4; q++) accS[i][j][q] = 0.f;

#pragma unroll
        for (int ks = 0; ks < 8; ks++) {
            uint32_t ah[2][4], al[2][4], bh[4][2], bl[4][2];
#pragma unroll
            for (int mi = 0; mi < 2; mi++) {
                const uint32_t off =
                    (uint32_t)((m_off + mi * 16 + a_row) * ALDQ + ks * 16 + a_kh) * 2;
                ldsm_x4(ah[mi][0], ah[mi][1], ah[mi][2], ah[mi][3], sb + A_QH + off);
                ldsm_x4(al[mi][0], al[mi][1], al[mi][2], al[mi][3], sb + A_QL + off);
            }
#pragma unroll
            for (int nb = 0; nb < 2; nb++) {
                const uint32_t off =
                    (uint32_t)((nS + nb * 16 + b_row) * ALDQ + ks * 16 + b_kh) * 2;
                ldsm_x4(bh[2 * nb][0], bh[2 * nb][1], bh[2 * nb + 1][0], bh[2 * nb + 1][1],
                        sb + A_KH + off);
                ldsm_x4(bl[2 * nb][0], bl[2 * nb][1], bl[2 * nb + 1][0], bl[2 * nb + 1][1],
                        sb + A_KL + off);
            }
#pragma unroll
            for (int mi = 0; mi < 2; mi++)
#pragma unroll
                for (int ni = 0; ni < 4; ni++) {
                    mma_bf16(accS[mi][ni], ah[mi], bh[ni]);
                    mma_bf16(accS[mi][ni], ah[mi], bl[ni]);
                    mma_bf16(accS[mi][ni], al[mi], bh[ni]);
                }
        }

#pragma unroll
        for (int mi = 0; mi < 2; mi++)
#pragma unroll
            for (int ni = 0; ni < 4; ni++) {
                const int row = m_off + mi * 16 + erow;
                const int col = nS + ni * 8 + ecol;
                Sp[row * ALDS + col]           = accS[mi][ni][0] * SCL2E;
                Sp[row * ALDS + col + 1]       = accS[mi][ni][1] * SCL2E;
                Sp[(row + 8) * ALDS + col]     = accS[mi][ni][2] * SCL2E;
                Sp[(row + 8) * ALDS + col + 1] = accS[mi][ni][3] * SCL2E;
            }
        __syncthreads();

        {
            const int row = tid & 127, part = tid >> 7;
            const int cb = part * 32;
            float mx = -1e30f;
#pragma unroll
            for (int c = 0; c < 32; c++) {
                const int cc = cb + c;
                float s = Sp[row * ALDS + cc];
                if (k0 + cc > q0 + row) s = -1e30f;
                mx = fmaxf(mx, s);
            }
            red[part * 128 + row] = mx;
            __syncthreads();
            if (part == 0) {
                float mo = m_s[row];
                float mn = fmaxf(mo, fmaxf(red[row], red[128 + row]));
                m_s[row] = mn;
                f_s[row] = fexp2(mo - mn);
            }
            __syncthreads();
            const float mrow = m_s[row];
            float sum = 0.f;
#pragma unroll
            for (int c = 0; c < 16; c++) {
                const int cc = cb + c * 2;
                float s0 = Sp[row * ALDS + cc];
                float s1 = Sp[row * ALDS + cc + 1];
                float p0 = (k0 + cc     > q0 + row) ? 0.f : fexp2(s0 - mrow);
                float p1 = (k0 + cc + 1 > q0 + row) ? 0.f : fexp2(s1 - mrow);
                sum += p0 + p1;
                __nv_bfloat16 h0 = __float2bfloat16(p0);
                __nv_bfloat16 h1 = __float2bfloat16(p1);
                __nv_bfloat162 hp; hp.x = h0; hp.y = h1;
                *(__nv_bfloat162*)(PhP + row * ALDP + cc) = hp;
                __nv_bfloat162 lp;
                lp.x = __float2bfloat16(p0 - __bfloat162float(h0));
                lp.y = __float2bfloat16(p1 - __bfloat162float(h1));
                *(__nv_bfloat162*)(PlP + row * ALDP + cc) = lp;
            }
            red[part * 128 + row] = sum;
            __syncthreads();
            if (part == 0)
                l_s[row] = l_s[row] * f_s[row] + red[row] + red[128 + row];
        }
        __syncthreads();

#pragma unroll
        for (int mi = 0; mi < 2; mi++) {
            const float f0 = f_s[m_off + mi * 16 + erow];
            const float f1 = f_s[m_off + mi * 16 + erow + 8];
#pragma unroll
            for (int ni = 0; ni < 8; ni++) {
                accO[mi][ni][0] *= f0; accO[mi][ni][1] *= f0;
                accO[mi][ni][2] *= f1; accO[mi][ni][3] *= f1;
            }
        }
#pragma unroll
        for (int kk = 0; kk < 4; kk++) {
            uint32_t ph[2][4], pl[2][4], vh[8][2], vl[8][2];
#pragma unroll
            for (int mi = 0; mi < 2; mi++) {
                const uint32_t off =
                    (uint32_t)((m_off + mi * 16 + a_row) * ALDP + kk * 16 + a_kh) * 2;
                ldsm_x4(ph[mi][0], ph[mi][1], ph[mi][2], ph[mi][3], sb + A_PH + off);
                ldsm_x4(pl[mi][0], pl[mi][1], pl[mi][2], pl[mi][3], sb + A_PL + off);
            }
#pragma unroll
            for (int nb = 0; nb < 4; nb++) {
                const int vr = kk * 16 + ((lane >> 3) & 1) * 8 + (lane & 7);
                const int vc = nO + nb * 16 + ((lane >> 4) & 1) * 8;
                const uint32_t off = (uint32_t)(vr * ALDQ + vc) * 2;
                ldsm_x4_t(vh[2 * nb][0], vh[2 * nb][1], vh[2 * nb + 1][0], vh[2 * nb + 1][1],
                          sb + A_VH + off);
                ldsm_x4_t(vl[2 * nb][0], vl[2 * nb][1], vl[2 * nb + 1][0], vl[2 * nb + 1][1],
                          sb + A_VL + off);
            }
#pragma unroll
            for (int mi = 0; mi < 2; mi++)
#pragma unroll
                for (int ni = 0; ni < 8; ni++) {
                    mma_bf16(accO[mi][ni], ph[mi], vh[ni]);
                    mma_bf16(accO[mi][ni], ph[mi], vl[ni]);
                    mma_bf16(accO[mi][ni], pl[mi], vh[ni]);
                }
        }
        __syncthreads();
    }

#pragma unroll
    for (int mi = 0; mi < 2; mi++) {
        const int r0 = m_off + mi * 16 + erow, r1 = r0 + 8;
        const float i0 = 1.0f / l_s[r0];
        const float i1 = 1.0f / l_s[r1];
        const size_t g0 = ((size_t)(b * SEQ + q0 + r0)) * (NH * HD) + h * HD;
        const size_t g1 = ((size_t)(b * SEQ + q0 + r1)) * (NH * HD) + h * HD;
#pragma unroll
        for (int ni = 0; ni < 8; ni++) {
            const int col = nO + ni * 8 + ecol;
            float o0 = accO[mi][ni][0] * i0, o1 = accO[mi][ni][1] * i0;
            float o2 = accO[mi][ni][2] * i1, o3 = accO[mi][ni][3] * i1;
            __nv_bfloat16 h0 = __float2bfloat16(o0), h1 = __float2bfloat16(o1);
            __nv_bfloat16 h2 = __float2bfloat16(o2), h3 = __float2bfloat16(o3);
            __nv_bfloat162 t;
            t.x = h0; t.y = h1; *(__nv_bfloat162*)(Oh_ + g0 + col) = t;
            t.x = __float2bfloat16(o0 - __bfloat162float(h0));
            t.y = __float2bfloat16(o1 - __bfloat162float(h1));
            *(__nv_bfloat162*)(Ol_ + g0 + col) = t;
            t.x = h2; t.y = h3; *(__nv_bfloat162*)(Oh_ + g1 + col) = t;
            t.x = __float2bfloat16(o2 - __bfloat162float(h2));
            t.y = __float2bfloat16(o3 - __bfloat162float(h3));
            *(__nv_bfloat162*)(Ol_ + g1 + col) = t;
        }
    }
}

// ============================================================
// Launch
// ============================================================
extern "C" void kernel_launch(void* const* d_in, const int* in_sizes, int n_in,
                              void* d_out, int out_size)
{
    (void)in_sizes; (void)n_in; (void)out_size;
    const float* x  = (const float*)d_in[0];
    const float* Wq = (const float*)d_in[2];
    const float* Wk = (const float*)d_in[3];
    const float* Wv = (const float*)d_in[4];
    const float* Wo = (const float*)d_in[5];
    float* out = (float*)d_out;

    __nv_bfloat16 *xh, *xl, *wqh, *wql, *wkh, *wkl, *wvh, *wvl, *woh, *wol;
    __nv_bfloat16 *qsh, *qsl, *ksh, *ksl, *vsh, *vsl, *oh, *ol;
    cudaGetSymbolAddress((void**)&xh, g_xh);   cudaGetSymbolAddress((void**)&xl, g_xl);
    cudaGetSymbolAddress((void**)&wqh, g_wqh); cudaGetSymbolAddress((void**)&wql, g_wql);
    cudaGetSymbolAddress((void**)&wkh, g_wkh); cudaGetSymbolAddress((void**)&wkl, g_wkl);
    cudaGetSymbolAddress((void**)&wvh, g_wvh); cudaGetSymbolAddress((void**)&wvl, g_wvl);
    cudaGetSymbolAddress((void**)&woh, g_woh); cudaGetSymbolAddress((void**)&wol, g_wol);
    cudaGetSymbolAddress((void**)&qsh, g_qsh); cudaGetSymbolAddress((void**)&qsl, g_qsl);
    cudaGetSymbolAddress((void**)&ksh, g_ksh); cudaGetSymbolAddress((void**)&ksl, g_ksl);
    cudaGetSymbolAddress((void**)&vsh, g_vsh); cudaGetSymbolAddress((void**)&vsl, g_vsl);
    cudaGetSymbolAddress((void**)&oh, g_oh);   cudaGetSymbolAddress((void**)&ol, g_ol);

    const int M = BB * SEQ;        // 4096
    const int NX = M * HIDN;

    cudaFuncSetAttribute(gemm3, cudaFuncAttributeMaxDynamicSharedMemorySize, G3_SMEM);
    cudaFuncSetAttribute(attn_hmma, cudaFuncAttributeMaxDynamicSharedMemorySize, ATTN_SMEM_B);

    // #1..#3
    split_fp32<<<NX / 256, 256>>>(x, xh, xl, NX);
    transpose_split<<<dim3((NH * HD) / 32, HIDN / 32), dim3(32, 8)>>>(Wq, wqh, wql, HIDN, NH * HD);
    transpose_split<<<dim3((NKV * HD) / 32, HIDN / 32), dim3(32, 8)>>>(Wk, wkh, wkl, HIDN, NKV * HD);
    // #4: Q projection (ncu-profiled slot) -> split bf16 head-major
    gemm3<<<dim3((NH * HD) / 128, M / 128), 512, G3_SMEM>>>(
        xh, xl, wqh, wql, nullptr, qsh, qsl, NH * HD, HIDN, NH, 1);
    // #5..#8
    transpose_split<<<dim3((NKV * HD) / 32, HIDN / 32), dim3(32, 8)>>>(Wv, wvh, wvl, HIDN, NKV * HD);
    gemm3<<<dim3((NKV * HD) / 128, M / 128), 512, G3_SMEM>>>(
        xh, xl, wkh, wkl, nullptr, ksh, ksl, NKV * HD, HIDN, NKV, 1);
    gemm3<<<dim3((NKV * HD) / 128, M / 128), 512, G3_SMEM>>>(
        xh, xl, wvh, wvl, nullptr, vsh, vsl, NKV * HD, HIDN, NKV, 1);
    transpose_split<<<dim3(HIDN / 32, (NH * HD) / 32), dim3(32, 8)>>>(Wo, woh, wol, NH * HD, HIDN);
    // #9..#10: RoPE in-place on split bf16
    rope_inplace<<<BB * NH * SEQ,  64>>>(qsh, qsl);
    rope_inplace<<<BB * NKV * SEQ, 64>>>(ksh, ksl);
    // #11
    attn_hmma<<<dim3(SEQ / 128, NH, BB), 256, ATTN_SMEM_B>>>(qsh, qsl, ksh, ksl, vsh, vsl, oh, ol);
    // #12: output projection -> fp32 d_out
    gemm3<<<dim3(HIDN / 128, M / 128), 512, G3_SMEM>>>(
        oh, ol, woh, wol, out, nullptr, nullptr, HIDN, NH * HD, 0, 0);
}

// round 12
// speedup vs baseline: 1.0989x; 1.0989x over previous
#include <cuda_runtime.h>
#include <cuda_bf16.h>
#include <math.h>
#include <cstdint>

#define BB   2
#define SEQ  2048
#define HIDN 2048
#define NH   16
#define NKV  4
#define HD   128

// ============================================================
// helpers
// ============================================================
__device__ __forceinline__ uint32_t smem_u32(const void* p) {
    uint32_t a;
    asm("{ .reg .u64 t; cvta.to.shared.u64 t, %1; cvt.u32.u64 %0, t; }" : "=r"(a) : "l"(p));
    return a;
}
__device__ __forceinline__ void ldsm_x4(uint32_t& r0, uint32_t& r1, uint32_t& r2, uint32_t& r3,
                                        uint32_t addr) {
    asm volatile("ldmatrix.sync.aligned.m8n8.x4.shared.b16 {%0,%1,%2,%3}, [%4];"
                 : "=r"(r0), "=r"(r1), "=r"(r2), "=r"(r3) : "r"(addr));
}
__device__ __forceinline__ void ldsm_x4_t(uint32_t& r0, uint32_t& r1, uint32_t& r2, uint32_t& r3,
                                          uint32_t addr) {
    asm volatile("ldmatrix.sync.aligned.m8n8.x4.trans.shared.b16 {%0,%1,%2,%3}, [%4];"
                 : "=r"(r0), "=r"(r1), "=r"(r2), "=r"(r3) : "r"(addr));
}
__device__ __forceinline__ void mma_bf16(float* c, const uint32_t* a, const uint32_t* b) {
    asm volatile("mma.sync.aligned.m16n8k16.row.col.f32.bf16.bf16.f32 "
                 "{%0,%1,%2,%3}, {%4,%5,%6,%7}, {%8,%9}, {%0,%1,%2,%3};"
                 : "+f"(c[0]), "+f"(c[1]), "+f"(c[2]), "+f"(c[3])
                 : "r"(a[0]), "r"(a[1]), "r"(a[2]), "r"(a[3]), "r"(b[0]), "r"(b[1]));
}
__device__ __forceinline__ void cp_async16(uint32_t saddr, const void* gptr) {
    asm volatile("cp.async.cg.shared.global [%0], [%1], 16;"
                 :: "r"(saddr), "l"(__cvta_generic_to_global(gptr)));
}
// fast 2^t on the FMA pipe, t <= 0
__device__ __forceinline__ float fexp2(float t) {
    t = fmaxf(t, -126.0f);
    float fi = floorf(t);
    float f = t - fi;
    float p =             1.5403530e-4f;
    p = fmaf(p, f, 1.3333558e-3f);
    p = fmaf(p, f, 9.6181291e-3f);
    p = fmaf(p, f, 5.5504109e-2f);
    p = fmaf(p, f, 2.4022651e-1f);
    p = fmaf(p, f, 6.9314718e-1f);
    p = fmaf(p, f, 1.0f);
    return p * __int_as_float(((int)fi + 127) << 23);
}

// -------- scratch (device globals) --------
__device__ __nv_bfloat16 g_xh[(size_t)BB * SEQ * HIDN], g_xl[(size_t)BB * SEQ * HIDN];
__device__ __nv_bfloat16 g_wqh[(size_t)HIDN * NH * HD], g_wql[(size_t)HIDN * NH * HD];
__device__ __nv_bfloat16 g_wkh[(size_t)HIDN * NKV * HD], g_wkl[(size_t)HIDN * NKV * HD];
__device__ __nv_bfloat16 g_wvh[(size_t)HIDN * NKV * HD], g_wvl[(size_t)HIDN * NKV * HD];
__device__ __nv_bfloat16 g_woh[(size_t)NH * HD * HIDN], g_wol[(size_t)NH * HD * HIDN];

// head-major split operands for attention: [b, head, s, d]
__device__ __nv_bfloat16 g_qsh[(size_t)BB * NH * SEQ * HD],  g_qsl[(size_t)BB * NH * SEQ * HD];
__device__ __nv_bfloat16 g_ksh[(size_t)BB * NKV * SEQ * HD], g_ksl[(size_t)BB * NKV * SEQ * HD];
__device__ __nv_bfloat16 g_vsh[(size_t)BB * NKV * SEQ * HD], g_vsl[(size_t)BB * NKV * SEQ * HD];
// attention output, split, [B*S, H*D]
__device__ __nv_bfloat16 g_oh[(size_t)BB * SEQ * NH * HD],  g_ol[(size_t)BB * SEQ * NH * HD];

// ============================================================
// fp32 -> (hi, lo) bf16 split
// ============================================================
__global__ void split_fp32(const float* __restrict__ x,
                           __nv_bfloat16* __restrict__ h, __nv_bfloat16* __restrict__ l, int n)
{
    int i = blockIdx.x * blockDim.x + threadIdx.x;
    if (i < n) {
        float v = x[i];
        __nv_bfloat16 hi = __float2bfloat16(v);
        h[i] = hi;
        l[i] = __float2bfloat16(v - __bfloat162float(hi));
    }
}

// ============================================================
// W[K,N] fp32 -> Wt_hi/Wt_lo [N,K] bf16 (transpose + split)
// ============================================================
__global__ void transpose_split(const float* __restrict__ W,
                                __nv_bfloat16* __restrict__ Th, __nv_bfloat16* __restrict__ Tl,
                                int K, int N)
{
    __shared__ float t[32][33];
    const int n0 = blockIdx.x * 32, k0 = blockIdx.y * 32;
    const int tx = threadIdx.x, ty = threadIdx.y;
    for (int i = ty; i < 32; i += 8)
        t[i][tx] = W[(size_t)(k0 + i) * N + n0 + tx];
    __syncthreads();
    for (int i = ty; i < 32; i += 8) {
        float v = t[tx][i];
        __nv_bfloat16 hi = __float2bfloat16(v);
        float r = v - __bfloat162float(hi);
        Th[(size_t)(n0 + i) * K + k0 + tx] = hi;
        Tl[(size_t)(n0 + i) * K + k0 + tx] = __float2bfloat16(r);
    }
}

#define LDA 40

// ============================================================
// gemm3: 128x128 CTA tile, 128 threads / 4 warps (2x2),
// 64x64 warp tile (min fragment redundancy: 1.6x),
// BK=32, 2-stage cp.async, 2 CTAs/SM for latency hiding.
// C = (Ah+Al) @ (Bh+Bl)^T via 3-term split, fp32 accum.
// Epilogue: epi==0 -> fp32 row-major C.
//           epi==1 -> split bf16 head-major [b, n>>7, s, n&127].
// ============================================================
#define G3_TILE (128 * LDA * 2)       // 10240 B
#define G3_STAGE (4 * G3_TILE)        // 40960 B
#define G3_SMEM (2 * G3_STAGE)        // 81920 B (x2 CTAs = 160K/SM)

__global__ void __launch_bounds__(128, 2) gemm3(
    const __nv_bfloat16* __restrict__ Ah_, const __nv_bfloat16* __restrict__ Al_,
    const __nv_bfloat16* __restrict__ Bh_, const __nv_bfloat16* __restrict__ Bl_,
    float* __restrict__ Cf, __nv_bfloat16* __restrict__ Ch, __nv_bfloat16* __restrict__ Cl,
    int Nd, int Kd, int heads, int epi)
{
    extern __shared__ char sm[];
    const uint32_t sb = smem_u32(sm);
    const int tid = threadIdx.x, lane = tid & 31, wid = tid >> 5;
    const int m0 = blockIdx.y * 128, n0 = blockIdx.x * 128;
    const int m_off = (wid >> 1) * 64;   // 0 or 64
    const int n_off = (wid & 1) * 64;    // 0 or 64

    const int r0 = tid >> 2;             // 0..31
    const int c8 = (tid & 3) * 8;        // 0,8,16,24

    const __nv_bfloat16* gp[4] = {
        Ah_ + (size_t)m0 * Kd, Al_ + (size_t)m0 * Kd,
        Bh_ + (size_t)n0 * Kd, Bl_ + (size_t)n0 * Kd };

    const int nchunk = Kd >> 5;

    auto load_chunk = [&](int c) {
        const int k0 = c << 5;
        const uint32_t stg = sb + (uint32_t)(c & 1) * G3_STAGE;
#pragma unroll
        for (int t = 0; t < 4; t++) {
#pragma unroll
            for (int p = 0; p < 4; p++) {
                const int r = r0 + p * 32;
                cp_async16(stg + (uint32_t)t * G3_TILE + (uint32_t)(r * LDA + c8) * 2,
                           gp[t] + (size_t)r * Kd + k0 + c8);
            }
        }
        asm volatile("cp.async.commit_group;" ::: "memory");
    };

    const int a_row = ((lane >> 3) & 1) * 8 + (lane & 7);
    const int a_kh  = (lane >> 4) * 8;
    const int b_row = ((lane >> 4) & 1) * 8 + (lane & 7);
    const int b_kh  = ((lane >> 3) & 1) * 8;

    float acc[4][8][4];
#pragma unroll
    for (int i = 0; i < 4; i++)
#pragma unroll
        for (int j = 0; j < 8; j++)
#pragma unroll
            for (int q = 0; q < 4; q++) acc[i][j][q] = 0.f;

    load_chunk(0);
    for (int c = 0; c < nchunk; c++) {
        if (c + 1 < nchunk) {
            load_chunk(c + 1);
            asm volatile("cp.async.wait_group 1;" ::: "memory");
        } else {
            asm volatile("cp.async.wait_group 0;" ::: "memory");
        }
        __syncthreads();

        const uint32_t stg = sb + (uint32_t)(c & 1) * G3_STAGE;
        const uint32_t sAh = stg;
        const uint32_t sAl = stg + G3_TILE;
        const uint32_t sBh = stg + 2 * G3_TILE;
        const uint32_t sBl = stg + 3 * G3_TILE;

#pragma unroll
        for (int ks = 0; ks < 2; ks++) {
            uint32_t ah[4][4], al[4][4], bh[8][2], bl[8][2];
#pragma unroll
            for (int mi = 0; mi < 4; mi++) {
                const uint32_t off =
                    (uint32_t)((m_off + mi * 16 + a_row) * LDA + ks * 16 + a_kh) * 2;
                ldsm_x4(ah[mi][0], ah[mi][1], ah[mi][2], ah[mi][3], sAh + off);
                ldsm_x4(al[mi][0], al[mi][1], al[mi][2], al[mi][3], sAl + off);
            }
#pragma unroll
            for (int nb = 0; nb < 4; nb++) {
                const uint32_t off =
                    (uint32_t)((n_off + nb * 16 + b_row) * LDA + ks * 16 + b_kh) * 2;
                ldsm_x4(bh[2 * nb][0], bh[2 * nb][1], bh[2 * nb + 1][0], bh[2 * nb + 1][1],
                        sBh + off);
                ldsm_x4(bl[2 * nb][0], bl[2 * nb][1], bl[2 * nb + 1][0], bl[2 * nb + 1][1],
                        sBl + off);
            }
#pragma unroll
            for (int mi = 0; mi < 4; mi++)
#pragma unroll
                for (int ni = 0; ni < 8; ni++) {
                    mma_bf16(acc[mi][ni], ah[mi], bh[ni]);
                    mma_bf16(acc[mi][ni], ah[mi], bl[ni]);
                    mma_bf16(acc[mi][ni], al[mi], bh[ni]);
                }
        }
        __syncthreads();
    }

    const int erow = lane >> 2, ecol = (lane & 3) * 2;
    if (epi == 0) {
#pragma unroll
        for (int mi = 0; mi < 4; mi++)
#pragma unroll
            for (int ni = 0; ni < 8; ni++) {
                const int row = m0 + m_off + mi * 16 + erow;
                const int col = n0 + n_off + ni * 8 + ecol;
                float2 v0 = make_float2(acc[mi][ni][0], acc[mi][ni][1]);
                float2 v1 = make_float2(acc[mi][ni][2], acc[mi][ni][3]);
                *(float2*)(Cf + (size_t)row * Nd + col)       = v0;
                *(float2*)(Cf + (size_t)(row + 8) * Nd + col) = v1;
            }
    } else {
        // split bf16, head-major [b, h, s, d]; row = b*SEQ + s, col = h*HD + d
#pragma unroll
        for (int mi = 0; mi < 4; mi++)
#pragma unroll
            for (int ni = 0; ni < 8; ni++) {
                const int col = n0 + n_off + ni * 8 + ecol;
                const int hh = col >> 7, d = col & 127;
#pragma unroll
                for (int rr = 0; rr < 2; rr++) {
                    const int row = m0 + m_off + mi * 16 + erow + rr * 8;
                    const int bb = row >> 11, s = row & (SEQ - 1);
                    const size_t g = ((size_t)(bb * heads + hh) * SEQ + s) * HD + d;
                    float v0 = acc[mi][ni][rr * 2 + 0];
                    float v1 = acc[mi][ni][rr * 2 + 1];
                    __nv_bfloat16 h0 = __float2bfloat16(v0);
                    __nv_bfloat16 h1 = __float2bfloat16(v1);
                    __nv_bfloat162 hp; hp.x = h0; hp.y = h1;
                    *(__nv_bfloat162*)(Ch + g) = hp;
                    __nv_bfloat162 lp;
                    lp.x = __float2bfloat16(v0 - __bfloat162float(h0));
                    lp.y = __float2bfloat16(v1 - __bfloat162float(h1));
                    *(__nv_bfloat162*)(Cl + g) = lp;
                }
            }
    }
}

// ============================================================
// RoPE in-place on split bf16 head-major rows [*, 128]
// ============================================================
__global__ void rope_inplace(__nv_bfloat16* __restrict__ h, __nv_bfloat16* __restrict__ l)
{
    const int idx = blockIdx.x;            // (b*heads + hh)*SEQ + s
    const int s = idx & (SEQ - 1);
    const size_t base = (size_t)idx * HD;
    const int i = threadIdx.x;             // 0..63

    float x0 = __bfloat162float(h[base + 2 * i])     + __bfloat162float(l[base + 2 * i]);
    float x1 = __bfloat162float(h[base + 2 * i + 1]) + __bfloat162float(l[base + 2 * i + 1]);
    float inv = exp2f(-(float)i * (13.287712379549449f / 64.f));
    float ang = (float)s * inv;
    float sn, cs;
    sincosf(ang, &sn, &cs);
    float o0 = x0 * cs - x1 * sn;
    float o1 = x0 * sn + x1 * cs;
    __syncthreads();   // all reads before any writes
    __nv_bfloat16 h0 = __float2bfloat16(o0);
    __nv_bfloat16 h1 = __float2bfloat16(o1);
    h[base + i]      = h0;
    h[base + i + 64] = h1;
    l[base + i]      = __float2bfloat16(o0 - __bfloat162float(h0));
    l[base + i + 64] = __float2bfloat16(o1 - __bfloat162float(h1));
}

// ============================================================
// HMMA flash attention (unchanged from R6/R8)
// ============================================================
#define ALDQ 136
#define ALDS 73
#define ALDP 72
#define A_QH 0
#define A_QL (A_QH + 128 * ALDQ * 2)
#define A_KH (A_QL + 128 * ALDQ * 2)
#define A_KL (A_KH + 64 * ALDQ * 2)
#define A_VH (A_KL + 64 * ALDQ * 2)
#define A_VL (A_VH + 64 * ALDQ * 2)
#define A_SP (A_VL + 64 * ALDQ * 2)
#define A_PH (A_SP + 128 * ALDS * 4)
#define A_PL (A_PH + 128 * ALDP * 2)
#define A_MS (A_PL + 128 * ALDP * 2)
#define A_LS (A_MS + 512)
#define A_FS (A_LS + 512)
#define A_RED (A_FS + 512)
#define ATTN_SMEM_B (A_RED + 1024)

#define SCL2E 0.12751744f

__global__ void __launch_bounds__(256, 1) attn_hmma(
    const __nv_bfloat16* __restrict__ Qh_, const __nv_bfloat16* __restrict__ Ql_,
    const __nv_bfloat16* __restrict__ Kh_, const __nv_bfloat16* __restrict__ Kl_,
    const __nv_bfloat16* __restrict__ Vh_, const __nv_bfloat16* __restrict__ Vl_,
    __nv_bfloat16* __restrict__ Oh_, __nv_bfloat16* __restrict__ Ol_)
{
    extern __shared__ char sm[];
    const uint32_t sb = smem_u32(sm);
    float* Sp  = (float*)(sm + A_SP);
    float* m_s = (float*)(sm + A_MS);
    float* l_s = (float*)(sm + A_LS);
    float* f_s = (float*)(sm + A_FS);
    float* red = (float*)(sm + A_RED);
    __nv_bfloat16* PhP = (__nv_bfloat16*)(sm + A_PH);
    __nv_bfloat16* PlP = (__nv_bfloat16*)(sm + A_PL);

    const int qb = blockIdx.x, h = blockIdx.y, b = blockIdx.z;
    const int kvh = h >> 2;
    const int tid = threadIdx.x, lane = tid & 31, wid = tid >> 5;
    const int q0 = qb * 128;

    const size_t qg = ((size_t)(b * NH + h) * SEQ + q0) * HD;
    const size_t kg = (size_t)(b * NKV + kvh) * SEQ * HD;

    for (int i = tid; i < 128 * 16; i += 256) {
        int r = i >> 4, c = (i & 15) * 8;
        uint32_t so = (uint32_t)(r * ALDQ + c) * 2;
        cp_async16(sb + A_QH + so, Qh_ + qg + (size_t)r * HD + c);
        cp_async16(sb + A_QL + so, Ql_ + qg + (size_t)r * HD + c);
    }
    asm volatile("cp.async.commit_group;" ::: "memory");
    if (tid < 128) { m_s[tid] = -1e30f; l_s[tid] = 0.f; }

    float accO[2][8][4];
#pragma unroll
    for (int i = 0; i < 2; i++)
#pragma unroll
        for (int j = 0; j < 8; j++)
#pragma unroll
            for (int q = 0; q < 4; q++) accO[i][j][q] = 0.f;

    const int m_off = (wid >> 1) * 32;
    const int nS = (wid & 1) * 32;
    const int nO = (wid & 1) * 64;
    const int a_row = ((lane >> 3) & 1) * 8 + (lane & 7);
    const int a_kh  = (lane >> 4) * 8;
    const int b_row = ((lane >> 4) & 1) * 8 + (lane & 7);
    const int b_kh  = ((lane >> 3) & 1) * 8;
    const int erow = lane >> 2, ecol = (lane & 3) * 2;

    asm volatile("cp.async.wait_group 0;" ::: "memory");
    __syncthreads();

    const int ntiles = 2 * qb + 2;
    for (int jb = 0; jb < ntiles; jb++) {
        const int k0 = jb * 64;
        for (int i = tid; i < 64 * 16; i += 256) {
            int r = i >> 4, c = (i & 15) * 8;
            uint32_t so = (uint32_t)(r * ALDQ + c) * 2;
            const size_t g = kg + (size_t)(k0 + r) * HD + c;
            cp_async16(sb + A_KH + so, Kh_ + g);
            cp_async16(sb + A_KL + so, Kl_ + g);
            cp_async16(sb + A_VH + so, Vh_ + g);
            cp_async16(sb + A_VL + so, Vl_ + g);
        }
        asm volatile("cp.async.commit_group;" ::: "memory");
        asm volatile("cp.async.wait_group 0;" ::: "memory");
        __syncthreads();

        float accS[2][4][4];
#pragma unroll
        for (int i = 0; i < 2; i++)
#pragma unroll
            for (int j = 0; j < 4; j++)
#pragma unroll
                for (int q = 0; q < 4; q++) accS[i][j][q] = 0.f;

#pragma unroll
        for (int ks = 0; ks < 8; ks++) {
            uint32_t ah[2][4], al[2][4], bh[4][2], bl[4][2];
#pragma unroll
            for (int mi = 0; mi < 2; mi++) {
                const uint32_t off =
                    (uint32_t)((m_off + mi * 16 + a_row) * ALDQ + ks * 16 + a_kh) * 2;
                ldsm_x4(ah[mi][0], ah[mi][1], ah[mi][2], ah[mi][3], sb + A_QH + off);
                ldsm_x4(al[mi][0], al[mi][1], al[mi][2], al[mi][3], sb + A_QL + off);
            }
#pragma unroll
            for (int nb = 0; nb < 2; nb++) {
                const uint32_t off =
                    (uint32_t)((nS + nb * 16 + b_row) * ALDQ + ks * 16 + b_kh) * 2;
                ldsm_x4(bh[2 * nb][0], bh[2 * nb][1], bh[2 * nb + 1][0], bh[2 * nb + 1][1],
                        sb + A_KH + off);
                ldsm_x4(bl[2 * nb][0], bl[2 * nb][1], bl[2 * nb + 1][0], bl[2 * nb + 1][1],
                        sb + A_KL + off);
            }
#pragma unroll
            for (int mi = 0; mi < 2; mi++)
#pragma unroll
                for (int ni = 0; ni < 4; ni++) {
                    mma_bf16(accS[mi][ni], ah[mi], bh[ni]);
                    mma_bf16(accS[mi][ni], ah[mi], bl[ni]);
                    mma_bf16(accS[mi][ni], al[mi], bh[ni]);
                }
        }

#pragma unroll
        for (int mi = 0; mi < 2; mi++)
#pragma unroll
            for (int ni = 0; ni < 4; ni++) {
                const int row = m_off + mi * 16 + erow;
                const int col = nS + ni * 8 + ecol;
                Sp[row * ALDS + col]           = accS[mi][ni][0] * SCL2E;
                Sp[row * ALDS + col + 1]       = accS[mi][ni][1] * SCL2E;
                Sp[(row + 8) * ALDS + col]     = accS[mi][ni][2] * SCL2E;
                Sp[(row + 8) * ALDS + col + 1] = accS[mi][ni][3] * SCL2E;
            }
        __syncthreads();

        {
            const int row = tid & 127, part = tid >> 7;
            const int cb = part * 32;
            float mx = -1e30f;
#pragma unroll
            for (int c = 0; c < 32; c++) {
                const int cc = cb + c;
                float s = Sp[row * ALDS + cc];
                if (k0 + cc > q0 + row) s = -1e30f;
                mx = fmaxf(mx, s);
            }
            red[part * 128 + row] = mx;
            __syncthreads();
            if (part == 0) {
                float mo = m_s[row];
                float mn = fmaxf(mo, fmaxf(red[row], red[128 + row]));
                m_s[row] = mn;
                f_s[row] = fexp2(mo - mn);
            }
            __syncthreads();
            const float mrow = m_s[row];
            float sum = 0.f;
#pragma unroll
            for (int c = 0; c < 16; c++) {
                const int cc = cb + c * 2;
                float s0 = Sp[row * ALDS + cc];
                float s1 = Sp[row * ALDS + cc + 1];
                float p0 = (k0 + cc     > q0 + row) ? 0.f : fexp2(s0 - mrow);
                float p1 = (k0 + cc + 1 > q0 + row) ? 0.f : fexp2(s1 - mrow);
                sum += p0 + p1;
                __nv_bfloat16 h0 = __float2bfloat16(p0);
                __nv_bfloat16 h1 = __float2bfloat16(p1);
                __nv_bfloat162 hp; hp.x = h0; hp.y = h1;
                *(__nv_bfloat162*)(PhP + row * ALDP + cc) = hp;
                __nv_bfloat162 lp;
                lp.x = __float2bfloat16(p0 - __bfloat162float(h0));
                lp.y = __float2bfloat16(p1 - __bfloat162float(h1));
                *(__nv_bfloat162*)(PlP + row * ALDP + cc) = lp;
            }
            red[part * 128 + row] = sum;
            __syncthreads();
            if (part == 0)
                l_s[row] = l_s[row] * f_s[row] + red[row] + red[128 + row];
        }
        __syncthreads();

#pragma unroll
        for (int mi = 0; mi < 2; mi++) {
            const float f0 = f_s[m_off + mi * 16 + erow];
            const float f1 = f_s[m_off + mi * 16 + erow + 8];
#pragma unroll
            for (int ni = 0; ni < 8; ni++) {
                accO[mi][ni][0] *= f0; accO[mi][ni][1] *= f0;
                accO[mi][ni][2] *= f1; accO[mi][ni][3] *= f1;
            }
        }
#pragma unroll
        for (int kk = 0; kk < 4; kk++) {
            uint32_t ph[2][4], pl[2][4], vh[8][2], vl[8][2];
#pragma unroll
            for (int mi = 0; mi < 2; mi++) {
                const uint32_t off =
                    (uint32_t)((m_off + mi * 16 + a_row) * ALDP + kk * 16 + a_kh) * 2;
                ldsm_x4(ph[mi][0], ph[mi][1], ph[mi][2], ph[mi][3], sb + A_PH + off);
                ldsm_x4(pl[mi][0], pl[mi][1], pl[mi][2], pl[mi][3], sb + A_PL + off);
            }
#pragma unroll
            for (int nb = 0; nb < 4; nb++) {
                const int vr = kk * 16 + ((lane >> 3) & 1) * 8 + (lane & 7);
                const int vc = nO + nb * 16 + ((lane >> 4) & 1) * 8;
                const uint32_t off = (uint32_t)(vr * ALDQ + vc) * 2;
                ldsm_x4_t(vh[2 * nb][0], vh[2 * nb][1], vh[2 * nb + 1][0], vh[2 * nb + 1][1],
                          sb + A_VH + off);
                ldsm_x4_t(vl[2 * nb][0], vl[2 * nb][1], vl[2 * nb + 1][0], vl[2 * nb + 1][1],
                          sb + A_VL + off);
            }
#pragma unroll
            for (int mi = 0; mi < 2; mi++)
#pragma unroll
                for (int ni = 0; ni < 8; ni++) {
                    mma_bf16(accO[mi][ni], ph[mi], vh[ni]);
                    mma_bf16(accO[mi][ni], ph[mi], vl[ni]);
                    mma_bf16(accO[mi][ni], pl[mi], vh[ni]);
                }
        }
        __syncthreads();
    }

#pragma unroll
    for (int mi = 0; mi < 2; mi++) {
        const int r0 = m_off + mi * 16 + erow, r1 = r0 + 8;
        const float i0 = 1.0f / l_s[r0];
        const float i1 = 1.0f / l_s[r1];
        const size_t g0 = ((size_t)(b * SEQ + q0 + r0)) * (NH * HD) + h * HD;
        const size_t g1 = ((size_t)(b * SEQ + q0 + r1)) * (NH * HD) + h * HD;
#pragma unroll
        for (int ni = 0; ni < 8; ni++) {
            const int col = nO + ni * 8 + ecol;
            float o0 = accO[mi][ni][0] * i0, o1 = accO[mi][ni][1] * i0;
            float o2 = accO[mi][ni][2] * i1, o3 = accO[mi][ni][3] * i1;
            __nv_bfloat16 h0 = __float2bfloat16(o0), h1 = __float2bfloat16(o1);
            __nv_bfloat16 h2 = __float2bfloat16(o2), h3 = __float2bfloat16(o3);
            __nv_bfloat162 t;
            t.x = h0; t.y = h1; *(__nv_bfloat162*)(Oh_ + g0 + col) = t;
            t.x = __float2bfloat16(o0 - __bfloat162float(h0));
            t.y = __float2bfloat16(o1 - __bfloat162float(h1));
            *(__nv_bfloat162*)(Ol_ + g0 + col) = t;
            t.x = h2; t.y = h3; *(__nv_bfloat162*)(Oh_ + g1 + col) = t;
            t.x = __float2bfloat16(o2 - __bfloat162float(h2));
            t.y = __float2bfloat16(o3 - __bfloat162float(h3));
            *(__nv_bfloat162*)(Ol_ + g1 + col) = t;
        }
    }
}

// ============================================================
// Launch
// ============================================================
extern "C" void kernel_launch(void* const* d_in, const int* in_sizes, int n_in,
                              void* d_out, int out_size)
{
    (void)in_sizes; (void)n_in; (void)out_size;
    const float* x  = (const float*)d_in[0];
    const float* Wq = (const float*)d_in[2];
    const float* Wk = (const float*)d_in[3];
    const float* Wv = (const float*)d_in[4];
    const float* Wo = (const float*)d_in[5];
    float* out = (float*)d_out;

    __nv_bfloat16 *xh, *xl, *wqh, *wql, *wkh, *wkl, *wvh, *wvl, *woh, *wol;
    __nv_bfloat16 *qsh, *qsl, *ksh, *ksl, *vsh, *vsl, *oh, *ol;
    cudaGetSymbolAddress((void**)&xh, g_xh);   cudaGetSymbolAddress((void**)&xl, g_xl);
    cudaGetSymbolAddress((void**)&wqh, g_wqh); cudaGetSymbolAddress((void**)&wql, g_wql);
    cudaGetSymbolAddress((void**)&wkh, g_wkh); cudaGetSymbolAddress((void**)&wkl, g_wkl);
    cudaGetSymbolAddress((void**)&wvh, g_wvh); cudaGetSymbolAddress((void**)&wvl, g_wvl);
    cudaGetSymbolAddress((void**)&woh, g_woh); cudaGetSymbolAddress((void**)&wol, g_wol);
    cudaGetSymbolAddress((void**)&qsh, g_qsh); cudaGetSymbolAddress((void**)&qsl, g_qsl);
    cudaGetSymbolAddress((void**)&ksh, g_ksh); cudaGetSymbolAddress((void**)&ksl, g_ksl);
    cudaGetSymbolAddress((void**)&vsh, g_vsh); cudaGetSymbolAddress((void**)&vsl, g_vsl);
    cudaGetSymbolAddress((void**)&oh, g_oh);   cudaGetSymbolAddress((void**)&ol, g_ol);

    const int M = BB * SEQ;        // 4096
    const int NX = M * HIDN;

    cudaFuncSetAttribute(gemm3, cudaFuncAttributeMaxDynamicSharedMemorySize, G3_SMEM);
    cudaFuncSetAttribute(attn_hmma, cudaFuncAttributeMaxDynamicSharedMemorySize, ATTN_SMEM_B);

    // #1..#3
    split_fp32<<<NX / 256, 256>>>(x, xh, xl, NX);
    transpose_split<<<dim3((NH * HD) / 32, HIDN / 32), dim3(32, 8)>>>(Wq, wqh, wql, HIDN, NH * HD);
    transpose_split<<<dim3((NKV * HD) / 32, HIDN / 32), dim3(32, 8)>>>(Wk, wkh, wkl, HIDN, NKV * HD);
    // #4: Q projection (ncu-profiled slot) -> split bf16 head-major
    gemm3<<<dim3((NH * HD) / 128, M / 128), 128, G3_SMEM>>>(
        xh, xl, wqh, wql, nullptr, qsh, qsl, NH * HD, HIDN, NH, 1);
    // #5..#8
    transpose_split<<<dim3((NKV * HD) / 32, HIDN / 32), dim3(32, 8)>>>(Wv, wvh, wvl, HIDN, NKV * HD);
    gemm3<<<dim3((NKV * HD) / 128, M / 128), 128, G3_SMEM>>>(
        xh, xl, wkh, wkl, nullptr, ksh, ksl, NKV * HD, HIDN, NKV, 1);
    gemm3<<<dim3((NKV * HD) / 128, M / 128), 128, G3_SMEM>>>(
        xh, xl, wvh, wvl, nullptr, vsh, vsl, NKV * HD, HIDN, NKV, 1);
    transpose_split<<<dim3(HIDN / 32, (NH * HD) / 32), dim3(32, 8)>>>(Wo, woh, wol, NH * HD, HIDN);
    // #9..#10: RoPE in-place on split bf16
    rope_inplace<<<BB * NH * SEQ,  64>>>(qsh, qsl);
    rope_inplace<<<BB * NKV * SEQ, 64>>>(ksh, ksl);
    // #11
    attn_hmma<<<dim3(SEQ / 128, NH, BB), 256, ATTN_SMEM_B>>>(qsh, qsl, ksh, ksl, vsh, vsl, oh, ol);
    // #12: output projection -> fp32 d_out
    gemm3<<<dim3(HIDN / 128, M / 128), 128, G3_SMEM>>>(
        oh, ol, woh, wol, out, nullptr, nullptr, HIDN, NH * HD, 0, 0);
}

// round 14
// speedup vs baseline: 1.2781x; 1.1630x over previous
#include <cuda_runtime.h>
#include <cuda_bf16.h>
#include <math.h>
#include <cstdint>

#define BB   2
#define SEQ  2048
#define HIDN 2048
#define NH   16
#define NKV  4
#define HD   128

// ============================================================
// helpers
// ============================================================
__device__ __forceinline__ uint32_t smem_u32(const void* p) {
    uint32_t a;
    asm("{ .reg .u64 t; cvta.to.shared.u64 t, %1; cvt.u32.u64 %0, t; }" : "=r"(a) : "l"(p));
    return a;
}
__device__ __forceinline__ void ldsm_x4(uint32_t& r0, uint32_t& r1, uint32_t& r2, uint32_t& r3,
                                        uint32_t addr) {
    asm volatile("ldmatrix.sync.aligned.m8n8.x4.shared.b16 {%0,%1,%2,%3}, [%4];"
                 : "=r"(r0), "=r"(r1), "=r"(r2), "=r"(r3) : "r"(addr));
}
__device__ __forceinline__ void ldsm_x4_t(uint32_t& r0, uint32_t& r1, uint32_t& r2, uint32_t& r3,
                                          uint32_t addr) {
    asm volatile("ldmatrix.sync.aligned.m8n8.x4.trans.shared.b16 {%0,%1,%2,%3}, [%4];"
                 : "=r"(r0), "=r"(r1), "=r"(r2), "=r"(r3) : "r"(addr));
}
__device__ __forceinline__ void mma_bf16(float* c, const uint32_t* a, const uint32_t* b) {
    asm volatile("mma.sync.aligned.m16n8k16.row.col.f32.bf16.bf16.f32 "
                 "{%0,%1,%2,%3}, {%4,%5,%6,%7}, {%8,%9}, {%0,%1,%2,%3};"
                 : "+f"(c[0]), "+f"(c[1]), "+f"(c[2]), "+f"(c[3])
                 : "r"(a[0]), "r"(a[1]), "r"(a[2]), "r"(a[3]), "r"(b[0]), "r"(b[1]));
}
__device__ __forceinline__ void cp_async16(uint32_t saddr, const void* gptr) {
    asm volatile("cp.async.cg.shared.global [%0], [%1], 16;"
                 :: "r"(saddr), "l"(__cvta_generic_to_global(gptr)));
}
// fast 2^t on the FMA pipe, t <= 0
__device__ __forceinline__ float fexp2(float t) {
    t = fmaxf(t, -126.0f);
    float fi = floorf(t);
    float f = t - fi;
    float p =             1.5403530e-4f;
    p = fmaf(p, f, 1.3333558e-3f);
    p = fmaf(p, f, 9.6181291e-3f);
    p = fmaf(p, f, 5.5504109e-2f);
    p = fmaf(p, f, 2.4022651e-1f);
    p = fmaf(p, f, 6.9314718e-1f);
    p = fmaf(p, f, 1.0f);
    return p * __int_as_float(((int)fi + 127) << 23);
}
__device__ __forceinline__ uint32_t pack_bf16x2(float lo, float hi) {
    __nv_bfloat162 t;
    t.x = __float2bfloat16(lo);
    t.y = __float2bfloat16(hi);
    return *(uint32_t*)&t;
}

// -------- scratch (device globals) --------
__device__ __nv_bfloat16 g_xh[(size_t)BB * SEQ * HIDN], g_xl[(size_t)BB * SEQ * HIDN];
__device__ __nv_bfloat16 g_wqh[(size_t)HIDN * NH * HD], g_wql[(size_t)HIDN * NH * HD];
__device__ __nv_bfloat16 g_wkh[(size_t)HIDN * NKV * HD], g_wkl[(size_t)HIDN * NKV * HD];
__device__ __nv_bfloat16 g_wvh[(size_t)HIDN * NKV * HD], g_wvl[(size_t)HIDN * NKV * HD];
__device__ __nv_bfloat16 g_woh[(size_t)NH * HD * HIDN], g_wol[(size_t)NH * HD * HIDN];

__device__ __nv_bfloat16 g_qsh[(size_t)BB * NH * SEQ * HD],  g_qsl[(size_t)BB * NH * SEQ * HD];
__device__ __nv_bfloat16 g_ksh[(size_t)BB * NKV * SEQ * HD], g_ksl[(size_t)BB * NKV * SEQ * HD];
__device__ __nv_bfloat16 g_vsh[(size_t)BB * NKV * SEQ * HD], g_vsl[(size_t)BB * NKV * SEQ * HD];
__device__ __nv_bfloat16 g_oh[(size_t)BB * SEQ * NH * HD],  g_ol[(size_t)BB * SEQ * NH * HD];

// ============================================================
// fp32 -> (hi, lo) bf16 split
// ============================================================
__global__ void split_fp32(const float* __restrict__ x,
                           __nv_bfloat16* __restrict__ h, __nv_bfloat16* __restrict__ l, int n)
{
    int i = blockIdx.x * blockDim.x + threadIdx.x;
    if (i < n) {
        float v = x[i];
        __nv_bfloat16 hi = __float2bfloat16(v);
        h[i] = hi;
        l[i] = __float2bfloat16(v - __bfloat162float(hi));
    }
}

// ============================================================
// W[K,N] fp32 -> Wt_hi/Wt_lo [N,K] bf16 (transpose + split)
// ============================================================
__global__ void transpose_split(const float* __restrict__ W,
                                __nv_bfloat16* __restrict__ Th, __nv_bfloat16* __restrict__ Tl,
                                int K, int N)
{
    __shared__ float t[32][33];
    const int n0 = blockIdx.x * 32, k0 = blockIdx.y * 32;
    const int tx = threadIdx.x, ty = threadIdx.y;
    for (int i = ty; i < 32; i += 8)
        t[i][tx] = W[(size_t)(k0 + i) * N + n0 + tx];
    __syncthreads();
    for (int i = ty; i < 32; i += 8) {
        float v = t[tx][i];
        __nv_bfloat16 hi = __float2bfloat16(v);
        float r = v - __bfloat162float(hi);
        Th[(size_t)(n0 + i) * K + k0 + tx] = hi;
        Tl[(size_t)(n0 + i) * K + k0 + tx] = __float2bfloat16(r);
    }
}

#define LDA 40

// ============================================================
// gemm3 (unchanged from R12): 128x128 CTA, 4 warps 64x64, 2 CTA/SM
// ============================================================
#define G3_TILE (128 * LDA * 2)
#define G3_STAGE (4 * G3_TILE)
#define G3_SMEM (2 * G3_STAGE)

__global__ void __launch_bounds__(128, 2) gemm3(
    const __nv_bfloat16* __restrict__ Ah_, const __nv_bfloat16* __restrict__ Al_,
    const __nv_bfloat16* __restrict__ Bh_, const __nv_bfloat16* __restrict__ Bl_,
    float* __restrict__ Cf, __nv_bfloat16* __restrict__ Ch, __nv_bfloat16* __restrict__ Cl,
    int Nd, int Kd, int heads, int epi)
{
    extern __shared__ char sm[];
    const uint32_t sb = smem_u32(sm);
    const int tid = threadIdx.x, lane = tid & 31, wid = tid >> 5;
    const int m0 = blockIdx.y * 128, n0 = blockIdx.x * 128;
    const int m_off = (wid >> 1) * 64;
    const int n_off = (wid & 1) * 64;

    const int r0 = tid >> 2;
    const int c8 = (tid & 3) * 8;

    const __nv_bfloat16* gp[4] = {
        Ah_ + (size_t)m0 * Kd, Al_ + (size_t)m0 * Kd,
        Bh_ + (size_t)n0 * Kd, Bl_ + (size_t)n0 * Kd };

    const int nchunk = Kd >> 5;

    auto load_chunk = [&](int c) {
        const int k0 = c << 5;
        const uint32_t stg = sb + (uint32_t)(c & 1) * G3_STAGE;
#pragma unroll
        for (int t = 0; t < 4; t++) {
#pragma unroll
            for (int p = 0; p < 4; p++) {
                const int r = r0 + p * 32;
                cp_async16(stg + (uint32_t)t * G3_TILE + (uint32_t)(r * LDA + c8) * 2,
                           gp[t] + (size_t)r * Kd + k0 + c8);
            }
        }
        asm volatile("cp.async.commit_group;" ::: "memory");
    };

    const int a_row = ((lane >> 3) & 1) * 8 + (lane & 7);
    const int a_kh  = (lane >> 4) * 8;
    const int b_row = ((lane >> 4) & 1) * 8 + (lane & 7);
    const int b_kh  = ((lane >> 3) & 1) * 8;

    float acc[4][8][4];
#pragma unroll
    for (int i = 0; i < 4; i++)
#pragma unroll
        for (int j = 0; j < 8; j++)
#pragma unroll
            for (int q = 0; q < 4; q++) acc[i][j][q] = 0.f;

    load_chunk(0);
    for (int c = 0; c < nchunk; c++) {
        if (c + 1 < nchunk) {
            load_chunk(c + 1);
            asm volatile("cp.async.wait_group 1;" ::: "memory");
        } else {
            asm volatile("cp.async.wait_group 0;" ::: "memory");
        }
        __syncthreads();

        const uint32_t stg = sb + (uint32_t)(c & 1) * G3_STAGE;
        const uint32_t sAh = stg;
        const uint32_t sAl = stg + G3_TILE;
        const uint32_t sBh = stg + 2 * G3_TILE;
        const uint32_t sBl = stg + 3 * G3_TILE;

#pragma unroll
        for (int ks = 0; ks < 2; ks++) {
            uint32_t ah[4][4], al[4][4], bh[8][2], bl[8][2];
#pragma unroll
            for (int mi = 0; mi < 4; mi++) {
                const uint32_t off =
                    (uint32_t)((m_off + mi * 16 + a_row) * LDA + ks * 16 + a_kh) * 2;
                ldsm_x4(ah[mi][0], ah[mi][1], ah[mi][2], ah[mi][3], sAh + off);
                ldsm_x4(al[mi][0], al[mi][1], al[mi][2], al[mi][3], sAl + off);
            }
#pragma unroll
            for (int nb = 0; nb < 4; nb++) {
                const uint32_t off =
                    (uint32_t)((n_off + nb * 16 + b_row) * LDA + ks * 16 + b_kh) * 2;
                ldsm_x4(bh[2 * nb][0], bh[2 * nb][1], bh[2 * nb + 1][0], bh[2 * nb + 1][1],
                        sBh + off);
                ldsm_x4(bl[2 * nb][0], bl[2 * nb][1], bl[2 * nb + 1][0], bl[2 * nb + 1][1],
                        sBl + off);
            }
#pragma unroll
            for (int mi = 0; mi < 4; mi++)
#pragma unroll
                for (int ni = 0; ni < 8; ni++) {
                    mma_bf16(acc[mi][ni], ah[mi], bh[ni]);
                    mma_bf16(acc[mi][ni], ah[mi], bl[ni]);
                    mma_bf16(acc[mi][ni], al[mi], bh[ni]);
                }
        }
        __syncthreads();
    }

    const int erow = lane >> 2, ecol = (lane & 3) * 2;
    if (epi == 0) {
#pragma unroll
        for (int mi = 0; mi < 4; mi++)
#pragma unroll
            for (int ni = 0; ni < 8; ni++) {
                const int row = m0 + m_off + mi * 16 + erow;
                const int col = n0 + n_off + ni * 8 + ecol;
                float2 v0 = make_float2(acc[mi][ni][0], acc[mi][ni][1]);
                float2 v1 = make_float2(acc[mi][ni][2], acc[mi][ni][3]);
                *(float2*)(Cf + (size_t)row * Nd + col)       = v0;
                *(float2*)(Cf + (size_t)(row + 8) * Nd + col) = v1;
            }
    } else {
#pragma unroll
        for (int mi = 0; mi < 4; mi++)
#pragma unroll
            for (int ni = 0; ni < 8; ni++) {
                const int col = n0 + n_off + ni * 8 + ecol;
                const int hh = col >> 7, d = col & 127;
#pragma unroll
                for (int rr = 0; rr < 2; rr++) {
                    const int row = m0 + m_off + mi * 16 + erow + rr * 8;
                    const int bb = row >> 11, s = row & (SEQ - 1);
                    const size_t g = ((size_t)(bb * heads + hh) * SEQ + s) * HD + d;
                    float v0 = acc[mi][ni][rr * 2 + 0];
                    float v1 = acc[mi][ni][rr * 2 + 1];
                    __nv_bfloat16 h0 = __float2bfloat16(v0);
                    __nv_bfloat16 h1 = __float2bfloat16(v1);
                    __nv_bfloat162 hp; hp.x = h0; hp.y = h1;
                    *(__nv_bfloat162*)(Ch + g) = hp;
                    __nv_bfloat162 lp;
                    lp.x = __float2bfloat16(v0 - __bfloat162float(h0));
                    lp.y = __float2bfloat16(v1 - __bfloat162float(h1));
                    *(__nv_bfloat162*)(Cl + g) = lp;
                }
            }
    }
}

// ============================================================
// RoPE in-place on split bf16 head-major rows [*, 128]
// ============================================================
__global__ void rope_inplace(__nv_bfloat16* __restrict__ h, __nv_bfloat16* __restrict__ l)
{
    const int idx = blockIdx.x;
    const int s = idx & (SEQ - 1);
    const size_t base = (size_t)idx * HD;
    const int i = threadIdx.x;

    float x0 = __bfloat162float(h[base + 2 * i])     + __bfloat162float(l[base + 2 * i]);
    float x1 = __bfloat162float(h[base + 2 * i + 1]) + __bfloat162float(l[base + 2 * i + 1]);
    float inv = exp2f(-(float)i * (13.287712379549449f / 64.f));
    float ang = (float)s * inv;
    float sn, cs;
    sincosf(ang, &sn, &cs);
    float o0 = x0 * cs - x1 * sn;
    float o1 = x0 * sn + x1 * cs;
    __syncthreads();
    __nv_bfloat16 h0 = __float2bfloat16(o0);
    __nv_bfloat16 h1 = __float2bfloat16(o1);
    h[base + i]      = h0;
    h[base + i + 64] = h1;
    l[base + i]      = __float2bfloat16(o0 - __bfloat162float(h0));
    l[base + i + 64] = __float2bfloat16(o1 - __bfloat162float(h1));
}

// ============================================================
// FA2-style HMMA flash attention: register-resident S/P/O.
// 256 threads / 8 warps; warp w owns q-rows [w*16, w*16+16),
// full 64-key tile width, full 128-d output.
// K/V double-buffered in smem (cp.async prefetch), Q single.
// ONE __syncthreads per KV tile; softmax via 4-lane shfl.
// 3-term split everywhere (Qh/Ql, Kh/Kl, Ph/Pl, Vh/Vl).
// ============================================================
#define ALDQ 136
#define NQH 0
#define NQL (128 * ALDQ * 2)            // 34816
#define NKV0 (2 * 128 * ALDQ * 2)       // 69632
#define NKVT (64 * ALDQ * 2)            // 17408
#define NATTN_SMEM (NKV0 + 8 * NKVT)    // 208896

#define SCL2E 0.12751744f   // (1/sqrt(128)) * log2(e)

__global__ void __launch_bounds__(256, 1) attn_hmma(
    const __nv_bfloat16* __restrict__ Qh_, const __nv_bfloat16* __restrict__ Ql_,
    const __nv_bfloat16* __restrict__ Kh_, const __nv_bfloat16* __restrict__ Kl_,
    const __nv_bfloat16* __restrict__ Vh_, const __nv_bfloat16* __restrict__ Vl_,
    __nv_bfloat16* __restrict__ Oh_, __nv_bfloat16* __restrict__ Ol_)
{
    extern __shared__ char sm[];
    const uint32_t sb = smem_u32(sm);

    const int qb = blockIdx.x, h = blockIdx.y, b = blockIdx.z;
    const int kvh = h >> 2;
    const int tid = threadIdx.x, lane = tid & 31, wid = tid >> 5;
    const int q0 = qb * 128;

    const size_t qg = ((size_t)(b * NH + h) * SEQ + q0) * HD;
    const size_t kg = (size_t)(b * NKV + kvh) * SEQ * HD;

    auto load_kv = [&](int jb, int buf) {
        const int k0 = jb * 64;
        const uint32_t base = sb + NKV0 + (uint32_t)buf * 4 * NKVT;
        for (int i = tid; i < 64 * 16; i += 256) {
            int r = i >> 4, cc = (i & 15) * 8;
            uint32_t so = (uint32_t)(r * ALDQ + cc) * 2;
            const size_t g = kg + (size_t)(k0 + r) * HD + cc;
            cp_async16(base + so,            Kh_ + g);
            cp_async16(base + NKVT + so,     Kl_ + g);
            cp_async16(base + 2 * NKVT + so, Vh_ + g);
            cp_async16(base + 3 * NKVT + so, Vl_ + g);
        }
        asm volatile("cp.async.commit_group;" ::: "memory");
    };

    // load Q (single buffer) + first K/V tile; one commit group
    for (int i = tid; i < 128 * 16; i += 256) {
        int r = i >> 4, cc = (i & 15) * 8;
        uint32_t so = (uint32_t)(r * ALDQ + cc) * 2;
        cp_async16(sb + NQH + so, Qh_ + qg + (size_t)r * HD + cc);
        cp_async16(sb + NQL + so, Ql_ + qg + (size_t)r * HD + cc);
    }
    load_kv(0, 0);

    // ldmatrix lane addressing
    const int a_row = ((lane >> 3) & 1) * 8 + (lane & 7);
    const int a_kh  = (lane >> 4) * 8;
    const int b_row = ((lane >> 4) & 1) * 8 + (lane & 7);
    const int b_kh  = ((lane >> 3) & 1) * 8;

    const int r0g = q0 + wid * 16 + (lane >> 2);   // global q row (half 0)
    const int cth = (lane & 3) * 2;                // thread col offset in n8 tile

    float o[16][4];
#pragma unroll
    for (int i = 0; i < 16; i++)
#pragma unroll
        for (int q = 0; q < 4; q++) o[i][q] = 0.f;
    float m0 = -1e30f, m1 = -1e30f, l0 = 0.f, l1 = 0.f;

    const int ntiles = 2 * qb + 2;
    for (int jb = 0; jb < ntiles; jb++) {
        asm volatile("cp.async.wait_group 0;" ::: "memory");
        __syncthreads();
        if (jb + 1 < ntiles) load_kv(jb + 1, (jb + 1) & 1);

        const uint32_t kb = sb + NKV0 + (uint32_t)(jb & 1) * 4 * NKVT;
        const int k0 = jb * 64;

        // ---- S = Q @ K^T : 16 x 64, k=128, 3-term ----
        float sa[8][4];
#pragma unroll
        for (int j = 0; j < 8; j++)
#pragma unroll
            for (int q = 0; q < 4; q++) sa[j][q] = 0.f;

#pragma unroll
        for (int ks = 0; ks < 8; ks++) {
            uint32_t qh[4], ql[4], bh[8][2], bl[8][2];
            const uint32_t qoff =
                (uint32_t)((wid * 16 + a_row) * ALDQ + ks * 16 + a_kh) * 2;
            ldsm_x4(qh[0], qh[1], qh[2], qh[3], sb + NQH + qoff);
            ldsm_x4(ql[0], ql[1], ql[2], ql[3], sb + NQL + qoff);
#pragma unroll
            for (int nb = 0; nb < 4; nb++) {
                const uint32_t koff =
                    (uint32_t)((nb * 16 + b_row) * ALDQ + ks * 16 + b_kh) * 2;
                ldsm_x4(bh[2 * nb][0], bh[2 * nb][1], bh[2 * nb + 1][0], bh[2 * nb + 1][1],
                        kb + koff);
                ldsm_x4(bl[2 * nb][0], bl[2 * nb][1], bl[2 * nb + 1][0], bl[2 * nb + 1][1],
                        kb + NKVT + koff);
            }
#pragma unroll
            for (int j = 0; j < 8; j++) {
                mma_bf16(sa[j], qh, bh[j]);
                mma_bf16(sa[j], qh, bl[j]);
                mma_bf16(sa[j], ql, bh[j]);
            }
        }

        // ---- scale + causal mask (in registers) ----
#pragma unroll
        for (int j = 0; j < 8; j++) {
            const int cb = k0 + j * 8 + cth;
            float s0 = sa[j][0] * SCL2E, s1 = sa[j][1] * SCL2E;
            float s2 = sa[j][2] * SCL2E, s3 = sa[j][3] * SCL2E;
            if (cb     > r0g)     s0 = -1e30f;
            if (cb + 1 > r0g)     s1 = -1e30f;
            if (cb     > r0g + 8) s2 = -1e30f;
            if (cb + 1 > r0g + 8) s3 = -1e30f;
            sa[j][0] = s0; sa[j][1] = s1; sa[j][2] = s2; sa[j][3] = s3;
        }

        // ---- warp-local online softmax (4-lane shfl reductions) ----
        float mx0 = -1e30f, mx1 = -1e30f;
#pragma unroll
        for (int j = 0; j < 8; j++) {
            mx0 = fmaxf(mx0, fmaxf(sa[j][0], sa[j][1]));
            mx1 = fmaxf(mx1, fmaxf(sa[j][2], sa[j][3]));
        }
        mx0 = fmaxf(mx0, __shfl_xor_sync(0xffffffff, mx0, 1));
        mx0 = fmaxf(mx0, __shfl_xor_sync(0xffffffff, mx0, 2));
        mx1 = fmaxf(mx1, __shfl_xor_sync(0xffffffff, mx1, 1));
        mx1 = fmaxf(mx1, __shfl_xor_sync(0xffffffff, mx1, 2));

        const float m0n = fmaxf(m0, mx0);
        const float m1n = fmaxf(m1, mx1);
        const float f0 = fexp2(m0 - m0n);
        const float f1 = fexp2(m1 - m1n);
        m0 = m0n; m1 = m1n;

        float sum0 = 0.f, sum1 = 0.f;
#pragma unroll
        for (int j = 0; j < 8; j++) {
            float p0 = fexp2(sa[j][0] - m0n);
            float p1 = fexp2(sa[j][1] - m0n);
            float p2 = fexp2(sa[j][2] - m1n);
            float p3 = fexp2(sa[j][3] - m1n);
            sum0 += p0 + p1; sum1 += p2 + p3;
            sa[j][0] = p0; sa[j][1] = p1; sa[j][2] = p2; sa[j][3] = p3;
        }
        sum0 += __shfl_xor_sync(0xffffffff, sum0, 1);
        sum0 += __shfl_xor_sync(0xffffffff, sum0, 2);
        sum1 += __shfl_xor_sync(0xffffffff, sum1, 1);
        sum1 += __shfl_xor_sync(0xffffffff, sum1, 2);
        l0 = l0 * f0 + sum0;
        l1 = l1 * f1 + sum1;

        // rescale O
#pragma unroll
        for (int nt = 0; nt < 16; nt++) {
            o[nt][0] *= f0; o[nt][1] *= f0;
            o[nt][2] *= f1; o[nt][3] *= f1;
        }

        // ---- build P fragments in registers (C layout == A layout) ----
        uint32_t ph[4][4], pl[4][4];
#pragma unroll
        for (int jk = 0; jk < 4; jk++) {
            const int j = 2 * jk, j2 = 2 * jk + 1;
            float v00 = sa[j][0],  v01 = sa[j][1],  v02 = sa[j][2],  v03 = sa[j][3];
            float v10 = sa[j2][0], v11 = sa[j2][1], v12 = sa[j2][2], v13 = sa[j2][3];
            ph[jk][0] = pack_bf16x2(v00, v01);
            ph[jk][1] = pack_bf16x2(v02, v03);
            ph[jk][2] = pack_bf16x2(v10, v11);
            ph[jk][3] = pack_bf16x2(v12, v13);
            pl[jk][0] = pack_bf16x2(v00 - __bfloat162float(__float2bfloat16(v00)),
                                    v01 - __bfloat162float(__float2bfloat16(v01)));
            pl[jk][1] = pack_bf16x2(v02 - __bfloat162float(__float2bfloat16(v02)),
                                    v03 - __bfloat162float(__float2bfloat16(v03)));
            pl[jk][2] = pack_bf16x2(v10 - __bfloat162float(__float2bfloat16(v10)),
                                    v11 - __bfloat162float(__float2bfloat16(v11)));
            pl[jk][3] = pack_bf16x2(v12 - __bfloat162float(__float2bfloat16(v12)),
                                    v13 - __bfloat162float(__float2bfloat16(v13)));
        }

        // ---- O += P @ V : 16 x 128, k=64, 3-term ----
        const uint32_t vbh = kb + 2 * NKVT;
        const uint32_t vbl = kb + 3 * NKVT;
#pragma unroll
        for (int kk = 0; kk < 4; kk++) {
#pragma unroll
            for (int half = 0; half < 2; half++) {
                uint32_t vh[8][2], vl[8][2];
#pragma unroll
                for (int nb = 0; nb < 4; nb++) {
                    const int vr = kk * 16 + ((lane >> 3) & 1) * 8 + (lane & 7);
                    const int vc = half * 64 + nb * 16 + ((lane >> 4) & 1) * 8;
                    const uint32_t off = (uint32_t)(vr * ALDQ + vc) * 2;
                    ldsm_x4_t(vh[2 * nb][0], vh[2 * nb][1],
                              vh[2 * nb + 1][0], vh[2 * nb + 1][1], vbh + off);
                    ldsm_x4_t(vl[2 * nb][0], vl[2 * nb][1],
                              vl[2 * nb + 1][0], vl[2 * nb + 1][1], vbl + off);
                }
#pragma unroll
                for (int nt = 0; nt < 8; nt++) {
                    const int ot = half * 8 + nt;
                    mma_bf16(o[ot], ph[kk], vh[nt]);
                    mma_bf16(o[ot], ph[kk], vl[nt]);
                    mma_bf16(o[ot], pl[kk], vh[nt]);
                }
            }
        }
    }

    // ---- finalize: O / l -> split bf16 output [B*S, H*D] ----
    const float i0 = 1.0f / l0;
    const float i1 = 1.0f / l1;
    const int row0 = q0 + wid * 16 + (lane >> 2);
    const size_t g0 = ((size_t)(b * SEQ + row0))     * (NH * HD) + h * HD;
    const size_t g1 = ((size_t)(b * SEQ + row0 + 8)) * (NH * HD) + h * HD;
#pragma unroll
    for (int nt = 0; nt < 16; nt++) {
        const int col = nt * 8 + cth;
        float v0 = o[nt][0] * i0, v1 = o[nt][1] * i0;
        float v2 = o[nt][2] * i1, v3 = o[nt][3] * i1;
        __nv_bfloat16 h0 = __float2bfloat16(v0), h1 = __float2bfloat16(v1);
        __nv_bfloat16 h2 = __float2bfloat16(v2), h3 = __float2bfloat16(v3);
        __nv_bfloat162 t;
        t.x = h0; t.y = h1; *(__nv_bfloat162*)(Oh_ + g0 + col) = t;
        t.x = __float2bfloat16(v0 - __bfloat162float(h0));
        t.y = __float2bfloat16(v1 - __bfloat162float(h1));
        *(__nv_bfloat162*)(Ol_ + g0 + col) = t;
        t.x = h2; t.y = h3; *(__nv_bfloat162*)(Oh_ + g1 + col) = t;
        t.x = __float2bfloat16(v2 - __bfloat162float(h2));
        t.y = __float2bfloat16(v3 - __bfloat162float(h3));
        *(__nv_bfloat162*)(Ol_ + g1 + col) = t;
    }
}

// ============================================================
// Launch
// ============================================================
extern "C" void kernel_launch(void* const* d_in, const int* in_sizes, int n_in,
                              void* d_out, int out_size)
{
    (void)in_sizes; (void)n_in; (void)out_size;
    const float* x  = (const float*)d_in[0];
    const float* Wq = (const float*)d_in[2];
    const float* Wk = (const float*)d_in[3];
    const float* Wv = (const float*)d_in[4];
    const float* Wo = (const float*)d_in[5];
    float* out = (float*)d_out;

    __nv_bfloat16 *xh, *xl, *wqh, *wql, *wkh, *wkl, *wvh, *wvl, *woh, *wol;
    __nv_bfloat16 *qsh, *qsl, *ksh, *ksl, *vsh, *vsl, *oh, *ol;
    cudaGetSymbolAddress((void**)&xh, g_xh);   cudaGetSymbolAddress((void**)&xl, g_xl);
    cudaGetSymbolAddress((void**)&wqh, g_wqh); cudaGetSymbolAddress((void**)&wql, g_wql);
    cudaGetSymbolAddress((void**)&wkh, g_wkh); cudaGetSymbolAddress((void**)&wkl, g_wkl);
    cudaGetSymbolAddress((void**)&wvh, g_wvh); cudaGetSymbolAddress((void**)&wvl, g_wvl);
    cudaGetSymbolAddress((void**)&woh, g_woh); cudaGetSymbolAddress((void**)&wol, g_wol);
    cudaGetSymbolAddress((void**)&qsh, g_qsh); cudaGetSymbolAddress((void**)&qsl, g_qsl);
    cudaGetSymbolAddress((void**)&ksh, g_ksh); cudaGetSymbolAddress((void**)&ksl, g_ksl);
    cudaGetSymbolAddress((void**)&vsh, g_vsh); cudaGetSymbolAddress((void**)&vsl, g_vsl);
    cudaGetSymbolAddress((void**)&oh, g_oh);   cudaGetSymbolAddress((void**)&ol, g_ol);

    const int M = BB * SEQ;        // 4096
    const int NX = M * HIDN;

    cudaFuncSetAttribute(gemm3, cudaFuncAttributeMaxDynamicSharedMemorySize, G3_SMEM);
    cudaFuncSetAttribute(attn_hmma, cudaFuncAttributeMaxDynamicSharedMemorySize, NATTN_SMEM);

    // #1..#3
    split_fp32<<<NX / 256, 256>>>(x, xh, xl, NX);
    transpose_split<<<dim3((NH * HD) / 32, HIDN / 32), dim3(32, 8)>>>(Wq, wqh, wql, HIDN, NH * HD);
    transpose_split<<<dim3((NKV * HD) / 32, HIDN / 32), dim3(32, 8)>>>(Wk, wkh, wkl, HIDN, NKV * HD);
    // #4: Q projection (ncu-profiled slot)
    gemm3<<<dim3((NH * HD) / 128, M / 128), 128, G3_SMEM>>>(
        xh, xl, wqh, wql, nullptr, qsh, qsl, NH * HD, HIDN, NH, 1);
    // #5..#8
    transpose_split<<<dim3((NKV * HD) / 32, HIDN / 32), dim3(32, 8)>>>(Wv, wvh, wvl, HIDN, NKV * HD);
    gemm3<<<dim3((NKV * HD) / 128, M / 128), 128, G3_SMEM>>>(
        xh, xl, wkh, wkl, nullptr, ksh, ksl, NKV * HD, HIDN, NKV, 1);
    gemm3<<<dim3((NKV * HD) / 128, M / 128), 128, G3_SMEM>>>(
        xh, xl, wvh, wvl, nullptr, vsh, vsl, NKV * HD, HIDN, NKV, 1);
    transpose_split<<<dim3(HIDN / 32, (NH * HD) / 32), dim3(32, 8)>>>(Wo, woh, wol, NH * HD, HIDN);
    // #9..#10: RoPE in-place
    rope_inplace<<<BB * NH * SEQ,  64>>>(qsh, qsl);
    rope_inplace<<<BB * NKV * SEQ, 64>>>(ksh, ksl);
    // #11: FA2-style attention
    attn_hmma<<<dim3(SEQ / 128, NH, BB), 256, NATTN_SMEM>>>(qsh, qsl, ksh, ksl, vsh, vsl, oh, ol);
    // #12: output projection -> fp32 d_out
    gemm3<<<dim3(HIDN / 128, M / 128), 128, G3_SMEM>>>(
        oh, ol, woh, wol, out, nullptr, nullptr, HIDN, NH * HD, 0, 0);
}